// round 15
// baseline (speedup 1.0000x reference)
#include <cuda_runtime.h>
#include <cuda_bf16.h>
#include <cstdint>

// ---------------- problem constants ----------------
#define N_PTS 4096
#define D_DIM 512
#define NP1   4097
#define SSTR  4128            // padded E row stride (floats)
#define PHI  0.0909090909090909091f
#define LOG_MU0   -8.4231266832367f   // log(0.9/4096)
#define LOG_MU_BIN -2.3025850929940f  // log(0.1)

#define RCHUNKS 32
#define RROWS   129
#define PSTR    4104

// GEMM staging: K=32 per stage, pitch 40 bf16 (80 B) -> conflict-free phases.
#define SP    40
#define SPB   80
#define TILB  10240
#define SLOT  (2 * TILB)              // A + B per stage (single bf16 pass)
#define PIPE  3
#define NSTG  16                      // K=512 / 32
#define GSMEM (PIPE * SLOT)           // 61440 B

// ---------------- scratch ----------------
__device__ __nv_bfloat16 g_h0[N_PTS * D_DIM];
__device__ __nv_bfloat16 g_h1[N_PTS * D_DIM];
__device__ float g_E[(size_t)NP1 * SSTR];
__device__ float g_eu[4104];
__device__ float g_ev[4104];
__device__ float g_part[RCHUNKS * PSTR];
__device__ float g_rpart[32 * 4096];    // per-column-block row partial sums (u1 fusion)

// ---------------- PTX helpers ----------------
__device__ __forceinline__ uint32_t smem_u32(const void* p) {
    uint32_t a;
    asm("{ .reg .u64 t; cvta.to.shared.u64 t, %1; cvt.u32.u64 %0, t; }" : "=r"(a) : "l"(p));
    return a;
}
#define CP_ASYNC16(dst, src) \
    asm volatile("cp.async.cg.shared.global [%0], [%1], 16;" :: "r"(dst), "l"(src) : "memory")
#define CP_COMMIT()  asm volatile("cp.async.commit_group;" ::: "memory")
#define CP_WAIT0()   asm volatile("cp.async.wait_group 0;" ::: "memory")
#define CP_WAIT1()   asm volatile("cp.async.wait_group 1;" ::: "memory")

__device__ __forceinline__ void ldmatrix_x4(uint32_t& r0, uint32_t& r1, uint32_t& r2,
                                            uint32_t& r3, uint32_t addr) {
    asm volatile("ldmatrix.sync.aligned.m8n8.x4.shared.b16 {%0,%1,%2,%3}, [%4];"
                 : "=r"(r0), "=r"(r1), "=r"(r2), "=r"(r3) : "r"(addr));
}
__device__ __forceinline__ void mma_16816(float* c, const uint32_t* a, const uint32_t* b) {
    asm volatile(
        "mma.sync.aligned.m16n8k16.row.col.f32.bf16.bf16.f32 "
        "{%0,%1,%2,%3}, {%4,%5,%6,%7}, {%8,%9}, {%0,%1,%2,%3};"
        : "+f"(c[0]), "+f"(c[1]), "+f"(c[2]), "+f"(c[3])
        : "r"(a[0]), "r"(a[1]), "r"(a[2]), "r"(a[3]), "r"(b[0]), "r"(b[1]));
}

// ---------------- normalization -> bf16 ----------------
__global__ void normalize_kernel(const float* __restrict__ ft0,
                                 const float* __restrict__ ft1) {
    int row = blockIdx.x;
    const float* src;
    __nv_bfloat16* dh;
    if (row < N_PTS) { src = ft0 + (size_t)row * D_DIM; dh = g_h0 + (size_t)row * D_DIM; }
    else { int r = row - N_PTS; src = ft1 + (size_t)r * D_DIM; dh = g_h1 + (size_t)r * D_DIM; }
    int t = threadIdx.x;
    float4 v = ((const float4*)src)[t];
    float ss = v.x * v.x + v.y * v.y + v.z * v.z + v.w * v.w;
    __shared__ float red[4];
    #pragma unroll
    for (int o = 16; o > 0; o >>= 1) ss += __shfl_xor_sync(0xffffffffu, ss, o);
    if ((t & 31) == 0) red[t >> 5] = ss;
    __syncthreads();
    float rn = rsqrtf(red[0] + red[1] + red[2] + red[3]);
    __nv_bfloat162 h0 = __floats2bfloat162_rn(v.x * rn, v.y * rn);
    __nv_bfloat162 h1 = __floats2bfloat162_rn(v.z * rn, v.w * rn);
    ((__nv_bfloat162*)dh)[t * 2 + 0] = h0;
    ((__nv_bfloat162*)dh)[t * 2 + 1] = h1;
}

// ---------------- dustbin fill + ev init ----------------
__global__ void setup_kernel(const float* __restrict__ bin_ptr) {
    float eb = __expf(10.0f * bin_ptr[0]);
    int i = blockIdx.x * blockDim.x + threadIdx.x;
    if (i < 4104) { g_eu[i] = 1.0f; g_ev[i] = 1.0f; }
    if (i < NP1)          g_E[(size_t)i * SSTR + N_PTS] = eb;
    else if (i < 2 * NP1) g_E[(size_t)N_PTS * SSTR + (i - NP1)] = eb;
}

// ---------------- HMMA GEMM (single bf16 pass): E = exp(10 * h0.h1) ----------------
// 128x128 CTA tile, 256 threads (2x4 warps of 64x32), PIPE=3, K=32/stage.
// Epilogue also emits per-CTA row partial sums for the fused first u-step.
__global__ void __launch_bounds__(256, 2) gemm_kernel() {
    extern __shared__ __align__(128) unsigned char dynsm[];
    const uint32_t s0 = smem_u32(dynsm);
    __shared__ float srow[128];

    int tid = threadIdx.x, lane = tid & 31, wid = tid >> 5;
    int warp_m = wid >> 2, warp_n = wid & 3;
    int row0 = blockIdx.y << 7, col0 = blockIdx.x << 7;

    if (tid < 128) srow[tid] = 0.0f;

    float acc[4][4][4] = {};

    int lr = (wid << 3) + (tid & 7);
    int lc = (tid >> 3) & 3;
    uint32_t so_base = (uint32_t)(lr * SPB + lc * 16);
    size_t   go_base = (size_t)lr * D_DIM + lc * 8;

    int a_row = (warp_m << 6) + (lane & 15);
    int a_kc  = (lane >> 4) << 3;
    int g     = lane >> 3;
    int b_rowg = (warp_n << 5) + ((g >> 1) << 3) + (lane & 7);
    int b_kcg  = (g & 1) << 3;
    int ks_x   = wid & 1;

    const size_t rbase = (size_t)row0 * D_DIM;
    const size_t cbase = (size_t)col0 * D_DIM;

    #define LOAD_STAGE(s) do {                                                 \
        int _kb = (s) << 5;                                                    \
        const __nv_bfloat16* _A = g_h0 + rbase + _kb;                          \
        const __nv_bfloat16* _B = g_h1 + cbase + _kb;                          \
        uint32_t _sa = s0 + (uint32_t)((s) % PIPE) * SLOT;                     \
        CP_ASYNC16(_sa + so_base,            _A + go_base);                    \
        CP_ASYNC16(_sa + so_base + 64 * SPB, _A + go_base + 64 * D_DIM);       \
        CP_ASYNC16(_sa + TILB + so_base,            _B + go_base);             \
        CP_ASYNC16(_sa + TILB + so_base + 64 * SPB, _B + go_base + 64 * D_DIM);\
        CP_COMMIT();                                                           \
    } while (0)

    LOAD_STAGE(0);
    LOAD_STAGE(1);

    for (int s = 0; s < NSTG; s++) {
        if (s == NSTG - 1) CP_WAIT0(); else CP_WAIT1();
        __syncthreads();
        if (s + 2 < NSTG) LOAD_STAGE(s + 2);

        uint32_t sa = s0 + (uint32_t)(s % PIPE) * SLOT;
        #pragma unroll
        for (int kk = 0; kk < 2; kk++) {
            int ks = kk ^ ks_x;
            uint32_t af[4][4], b1[4][2];
            #pragma unroll
            for (int mt = 0; mt < 4; mt++) {
                uint32_t addr = sa + (uint32_t)((a_row + mt * 16) * SPB
                                                + (ks * 16 + a_kc) * 2);
                ldmatrix_x4(af[mt][0], af[mt][1], af[mt][2], af[mt][3], addr);
            }
            #pragma unroll
            for (int p = 0; p < 2; p++) {
                uint32_t addr = sa + TILB + (uint32_t)((b_rowg + p * 16) * SPB
                                                       + (ks * 16 + b_kcg) * 2);
                ldmatrix_x4(b1[2 * p][0], b1[2 * p][1],
                            b1[2 * p + 1][0], b1[2 * p + 1][1], addr);
            }
            #pragma unroll
            for (int mt = 0; mt < 4; mt++)
                #pragma unroll
                for (int nt = 0; nt < 4; nt++)
                    mma_16816(acc[mt][nt], af[mt], b1[nt]);
        }
    }
    #undef LOAD_STAGE

    // epilogue: E = exp(10*acc); accumulate per-row tile sums
    int r_lo = row0 + (warp_m << 6) + (lane >> 2);
    int c_lo = col0 + (warp_n << 5) + ((lane & 3) << 1);
    float rs[4][2];
    #pragma unroll
    for (int mt = 0; mt < 4; mt++) { rs[mt][0] = 0.f; rs[mt][1] = 0.f; }
    #pragma unroll
    for (int mt = 0; mt < 4; mt++) {
        #pragma unroll
        for (int nt = 0; nt < 4; nt++) {
            float* p0 = g_E + (size_t)(r_lo + mt * 16) * SSTR + c_lo + nt * 8;
            float* p1 = p0 + 8 * SSTR;
            float e0 = __expf(10.f * acc[mt][nt][0]);
            float e1 = __expf(10.f * acc[mt][nt][1]);
            float e2 = __expf(10.f * acc[mt][nt][2]);
            float e3 = __expf(10.f * acc[mt][nt][3]);
            *(float2*)p0 = float2{e0, e1};
            *(float2*)p1 = float2{e2, e3};
            rs[mt][0] += e0 + e1;
            rs[mt][1] += e2 + e3;
        }
    }
    __syncthreads();      // srow init visible; pipeline smem traffic done
    #pragma unroll
    for (int mt = 0; mt < 4; mt++) {
        #pragma unroll
        for (int h = 0; h < 2; h++) {
            float v = rs[mt][h];
            v += __shfl_xor_sync(0xffffffffu, v, 1);
            v += __shfl_xor_sync(0xffffffffu, v, 2);
            if ((lane & 3) == 0)
                atomicAdd(&srow[(warp_m << 6) + mt * 16 + h * 8 + (lane >> 2)], v);
        }
    }
    __syncthreads();
    if (tid < 128)
        g_rpart[blockIdx.x * 4096 + row0 + tid] = srow[tid];
}

// ---------------- reduce row partials -> eu1 (first u half-step) ----------------
__global__ void reduce_u1(const float* __restrict__ bin_ptr) {
    float eb = __expf(10.0f * bin_ptr[0]);
    int j = blockIdx.x * 256 + threadIdx.x;
    if (j > N_PTS) return;
    float s;
    if (j < N_PTS) {
        s = eb;                               // dustbin column contribution
        #pragma unroll
        for (int c = 0; c < 32; c++) s += g_rpart[c * 4096 + j];
        g_eu[j] = __expf((LOG_MU0 - __logf(s)) * PHI);
    } else {
        s = 4097.0f * eb;                     // bin row: all entries = eb
        g_eu[j] = __expf((LOG_MU_BIN - __logf(s)) * PHI);
    }
}

// ---------------- Sinkhorn passes (MLP-batched loads) ----------------
__global__ void __launch_bounds__(256) u_pass() {
    int r = blockIdx.x;
    const float4* E4 = (const float4*)(g_E + (size_t)r * SSTR);
    const float4* V4 = (const float4*)g_ev;
    int t = threadIdx.x;
    float4 e0 = E4[t], e1 = E4[t + 256], e2 = E4[t + 512], e3 = E4[t + 768];
    float4 v0 = V4[t], v1 = V4[t + 256], v2 = V4[t + 512], v3 = V4[t + 768];
    float a0 = 0.f, a1 = 0.f, a2 = 0.f, a3 = 0.f;
    a0 = fmaf(e0.x, v0.x, a0); a1 = fmaf(e0.y, v0.y, a1);
    a2 = fmaf(e0.z, v0.z, a2); a3 = fmaf(e0.w, v0.w, a3);
    a0 = fmaf(e1.x, v1.x, a0); a1 = fmaf(e1.y, v1.y, a1);
    a2 = fmaf(e1.z, v1.z, a2); a3 = fmaf(e1.w, v1.w, a3);
    a0 = fmaf(e2.x, v2.x, a0); a1 = fmaf(e2.y, v2.y, a1);
    a2 = fmaf(e2.z, v2.z, a2); a3 = fmaf(e2.w, v2.w, a3);
    a0 = fmaf(e3.x, v3.x, a0); a1 = fmaf(e3.y, v3.y, a1);
    a2 = fmaf(e3.z, v3.z, a2); a3 = fmaf(e3.w, v3.w, a3);
    float acc = (a0 + a1) + (a2 + a3);
    if (t == 0)
        acc += g_E[(size_t)r * SSTR + N_PTS] * g_ev[N_PTS];
    __shared__ float red[8];
    #pragma unroll
    for (int o = 16; o > 0; o >>= 1) acc += __shfl_xor_sync(0xffffffffu, acc, o);
    if ((t & 31) == 0) red[t >> 5] = acc;
    __syncthreads();
    if (t == 0) {
        float tot = 0.f;
        #pragma unroll
        for (int w = 0; w < 8; w++) tot += red[w];
        float lm = (r < N_PTS) ? LOG_MU0 : LOG_MU_BIN;
        g_eu[r] = __expf((lm - __logf(tot)) * PHI);
    }
}

__global__ void __launch_bounds__(256) colsum() {
    int j  = blockIdx.x * 256 + threadIdx.x;
    int r0 = blockIdx.y * RROWS;
    int r1 = min(r0 + RROWS, NP1);
    __shared__ float ush[RROWS];
    for (int t = threadIdx.x; t < r1 - r0; t += 256) ush[t] = g_eu[r0 + t];
    __syncthreads();
    if (j >= NP1) return;
    const float* col = g_E + (size_t)r0 * SSTR + j;
    float a0 = 0.f, a1 = 0.f, a2 = 0.f, a3 = 0.f;
    float a4 = 0.f, a5 = 0.f, a6 = 0.f, a7 = 0.f;
    int n = r1 - r0, r = 0;
    for (; r + 8 <= n; r += 8) {
        float e0 = col[(size_t)(r + 0) * SSTR];
        float e1 = col[(size_t)(r + 1) * SSTR];
        float e2 = col[(size_t)(r + 2) * SSTR];
        float e3 = col[(size_t)(r + 3) * SSTR];
        float e4 = col[(size_t)(r + 4) * SSTR];
        float e5 = col[(size_t)(r + 5) * SSTR];
        float e6 = col[(size_t)(r + 6) * SSTR];
        float e7 = col[(size_t)(r + 7) * SSTR];
        a0 = fmaf(e0, ush[r + 0], a0);
        a1 = fmaf(e1, ush[r + 1], a1);
        a2 = fmaf(e2, ush[r + 2], a2);
        a3 = fmaf(e3, ush[r + 3], a3);
        a4 = fmaf(e4, ush[r + 4], a4);
        a5 = fmaf(e5, ush[r + 5], a5);
        a6 = fmaf(e6, ush[r + 6], a6);
        a7 = fmaf(e7, ush[r + 7], a7);
    }
    for (; r < n; r++) a0 = fmaf(col[(size_t)r * SSTR], ush[r], a0);
    g_part[blockIdx.y * PSTR + j] = ((a0 + a1) + (a2 + a3)) + ((a4 + a5) + (a6 + a7));
}

__global__ void v_final() {
    int j = blockIdx.x * 256 + threadIdx.x;
    if (j >= NP1) return;
    float tot = 0.f;
    #pragma unroll
    for (int c = 0; c < RCHUNKS; c++) tot += g_part[c * PSTR + j];
    float ln = (j < N_PTS) ? LOG_MU0 : LOG_MU_BIN;
    g_ev[j] = __expf((ln - __logf(tot)) * PHI);
}

// ---------------- fused last u-half-step + output ----------------
__global__ void __launch_bounds__(256) fused_final(float* __restrict__ out) {
    int r = blockIdx.x;
    const float* Er = g_E + (size_t)r * SSTR;
    const float4* E4 = (const float4*)Er;
    const float4* V4 = (const float4*)g_ev;
    int t = threadIdx.x;
    float4 e0 = E4[t], e1 = E4[t + 256], e2 = E4[t + 512], e3 = E4[t + 768];
    float4 v0 = V4[t], v1 = V4[t + 256], v2 = V4[t + 512], v3 = V4[t + 768];
    float a0 = 0.f, a1 = 0.f, a2 = 0.f, a3 = 0.f;
    a0 = fmaf(e0.x, v0.x, a0); a1 = fmaf(e0.y, v0.y, a1);
    a2 = fmaf(e0.z, v0.z, a2); a3 = fmaf(e0.w, v0.w, a3);
    a0 = fmaf(e1.x, v1.x, a0); a1 = fmaf(e1.y, v1.y, a1);
    a2 = fmaf(e1.z, v1.z, a2); a3 = fmaf(e1.w, v1.w, a3);
    a0 = fmaf(e2.x, v2.x, a0); a1 = fmaf(e2.y, v2.y, a1);
    a2 = fmaf(e2.z, v2.z, a2); a3 = fmaf(e2.w, v2.w, a3);
    a0 = fmaf(e3.x, v3.x, a0); a1 = fmaf(e3.y, v3.y, a1);
    a2 = fmaf(e3.z, v3.z, a2); a3 = fmaf(e3.w, v3.w, a3);
    float acc = (a0 + a1) + (a2 + a3);
    if (t == 0)
        acc += Er[N_PTS] * g_ev[N_PTS];
    __shared__ float red[8];
    __shared__ float s_eu;
    #pragma unroll
    for (int o = 16; o > 0; o >>= 1) acc += __shfl_xor_sync(0xffffffffu, acc, o);
    if ((t & 31) == 0) red[t >> 5] = acc;
    __syncthreads();
    if (t == 0) {
        float tot = 0.f;
        #pragma unroll
        for (int w = 0; w < 8; w++) tot += red[w];
        float lm = (r < N_PTS) ? LOG_MU0 : LOG_MU_BIN;
        s_eu = __expf((lm - __logf(tot)) * PHI);
    }
    __syncthreads();
    float eur = s_eu;
    float* orow = out + (size_t)r * NP1;
    const float* vv = g_ev;
    {
        int j0 = t * 4;
        orow[j0 + 0] = e0.x * eur * vv[j0 + 0];
        orow[j0 + 1] = e0.y * eur * vv[j0 + 1];
        orow[j0 + 2] = e0.z * eur * vv[j0 + 2];
        orow[j0 + 3] = e0.w * eur * vv[j0 + 3];
        int j1 = (t + 256) * 4;
        orow[j1 + 0] = e1.x * eur * vv[j1 + 0];
        orow[j1 + 1] = e1.y * eur * vv[j1 + 1];
        orow[j1 + 2] = e1.z * eur * vv[j1 + 2];
        orow[j1 + 3] = e1.w * eur * vv[j1 + 3];
        int j2 = (t + 512) * 4;
        orow[j2 + 0] = e2.x * eur * vv[j2 + 0];
        orow[j2 + 1] = e2.y * eur * vv[j2 + 1];
        orow[j2 + 2] = e2.z * eur * vv[j2 + 2];
        orow[j2 + 3] = e2.w * eur * vv[j2 + 3];
        int j3 = (t + 768) * 4;
        orow[j3 + 0] = e3.x * eur * vv[j3 + 0];
        orow[j3 + 1] = e3.y * eur * vv[j3 + 1];
        orow[j3 + 2] = e3.z * eur * vv[j3 + 2];
        orow[j3 + 3] = e3.w * eur * vv[j3 + 3];
    }
    if (t == 0) {
        float val = Er[N_PTS] * eur * vv[N_PTS];
        if (r == N_PTS) val = 0.0f;
        orow[N_PTS] = val;
    }
}

// ---------------- launch ----------------
extern "C" void kernel_launch(void* const* d_in, const int* in_sizes, int n_in,
                              void* d_out, int out_size) {
    const float* ft0 = (const float*)d_in[0];
    const float* ft1 = (const float*)d_in[1];
    const float* bin = (const float*)d_in[2];
    float* out = (float*)d_out;

    cudaFuncSetAttribute(gemm_kernel, cudaFuncAttributeMaxDynamicSharedMemorySize, GSMEM);

    normalize_kernel<<<2 * N_PTS, 128>>>(ft0, ft1);
    setup_kernel<<<(2 * NP1 + 255) / 256, 256>>>(bin);
    dim3 gg(32, 32);
    gemm_kernel<<<gg, 256, GSMEM>>>();

    // fused first half-step: row sums emitted by GEMM epilogue
    reduce_u1<<<17, 256>>>(bin);

    // remaining schedule: v1, u2, v2, (u3 fused with output)
    colsum<<<dim3(17, RCHUNKS), 256>>>();
    v_final<<<17, 256>>>();
    u_pass<<<NP1, 256>>>();
    colsum<<<dim3(17, RCHUNKS), 256>>>();
    v_final<<<17, 256>>>();
    fused_final<<<NP1, 256>>>(out);
}

// round 16
// speedup vs baseline: 1.0231x; 1.0231x over previous
#include <cuda_runtime.h>
#include <cuda_bf16.h>
#include <cstdint>

// ---------------- problem constants ----------------
#define N_PTS 4096
#define D_DIM 512
#define NP1   4097
#define SSTR  4128            // padded E row stride (floats)
#define PHI  0.0909090909090909091f
#define LOG_MU0   -8.4231266832367f   // log(0.9/4096)
#define LOG_MU_BIN -2.3025850929940f  // log(0.1)

#define RCHUNKS 32
#define RROWS   129
#define PSTR    4104

// GEMM staging: K=32 per stage, pitch 40 bf16 (80 B) -> conflict-free phases.
#define SP    40
#define SPB   80
#define TILB  10240
#define SLOT  (2 * TILB)              // A + B per stage (single bf16 pass)
#define PIPE  3
#define NSTG  16                      // K=512 / 32
#define GSMEM (PIPE * SLOT)           // 61440 B

// ---------------- scratch ----------------
__device__ __nv_bfloat16 g_h0[N_PTS * D_DIM];
__device__ __nv_bfloat16 g_h1[N_PTS * D_DIM];
__device__ float g_E[(size_t)NP1 * SSTR];
__device__ float g_eu[4104];
__device__ float g_ev[4104];
__device__ float g_part[RCHUNKS * PSTR];
__device__ float g_rowsum[4096];        // fused-u1 row sums (global atomics)

// ---------------- PTX helpers ----------------
__device__ __forceinline__ uint32_t smem_u32(const void* p) {
    uint32_t a;
    asm("{ .reg .u64 t; cvta.to.shared.u64 t, %1; cvt.u32.u64 %0, t; }" : "=r"(a) : "l"(p));
    return a;
}
#define CP_ASYNC16(dst, src) \
    asm volatile("cp.async.cg.shared.global [%0], [%1], 16;" :: "r"(dst), "l"(src) : "memory")
#define CP_COMMIT()  asm volatile("cp.async.commit_group;" ::: "memory")
#define CP_WAIT0()   asm volatile("cp.async.wait_group 0;" ::: "memory")
#define CP_WAIT1()   asm volatile("cp.async.wait_group 1;" ::: "memory")

__device__ __forceinline__ void ldmatrix_x4(uint32_t& r0, uint32_t& r1, uint32_t& r2,
                                            uint32_t& r3, uint32_t addr) {
    asm volatile("ldmatrix.sync.aligned.m8n8.x4.shared.b16 {%0,%1,%2,%3}, [%4];"
                 : "=r"(r0), "=r"(r1), "=r"(r2), "=r"(r3) : "r"(addr));
}
__device__ __forceinline__ void mma_16816(float* c, const uint32_t* a, const uint32_t* b) {
    asm volatile(
        "mma.sync.aligned.m16n8k16.row.col.f32.bf16.bf16.f32 "
        "{%0,%1,%2,%3}, {%4,%5,%6,%7}, {%8,%9}, {%0,%1,%2,%3};"
        : "+f"(c[0]), "+f"(c[1]), "+f"(c[2]), "+f"(c[3])
        : "r"(a[0]), "r"(a[1]), "r"(a[2]), "r"(a[3]), "r"(b[0]), "r"(b[1]));
}

// ---------------- normalization -> bf16 ----------------
__global__ void normalize_kernel(const float* __restrict__ ft0,
                                 const float* __restrict__ ft1) {
    int row = blockIdx.x;
    const float* src;
    __nv_bfloat16* dh;
    if (row < N_PTS) { src = ft0 + (size_t)row * D_DIM; dh = g_h0 + (size_t)row * D_DIM; }
    else { int r = row - N_PTS; src = ft1 + (size_t)r * D_DIM; dh = g_h1 + (size_t)r * D_DIM; }
    int t = threadIdx.x;
    float4 v = ((const float4*)src)[t];
    float ss = v.x * v.x + v.y * v.y + v.z * v.z + v.w * v.w;
    __shared__ float red[4];
    #pragma unroll
    for (int o = 16; o > 0; o >>= 1) ss += __shfl_xor_sync(0xffffffffu, ss, o);
    if ((t & 31) == 0) red[t >> 5] = ss;
    __syncthreads();
    float rn = rsqrtf(red[0] + red[1] + red[2] + red[3]);
    __nv_bfloat162 h0 = __floats2bfloat162_rn(v.x * rn, v.y * rn);
    __nv_bfloat162 h1 = __floats2bfloat162_rn(v.z * rn, v.w * rn);
    ((__nv_bfloat162*)dh)[t * 2 + 0] = h0;
    ((__nv_bfloat162*)dh)[t * 2 + 1] = h1;
}

// ---------------- dustbin fill + ev init + rowsum zero ----------------
__global__ void setup_kernel(const float* __restrict__ bin_ptr) {
    float eb = __expf(10.0f * bin_ptr[0]);
    int i = blockIdx.x * blockDim.x + threadIdx.x;
    if (i < 4104) { g_eu[i] = 1.0f; g_ev[i] = 1.0f; }
    if (i < 4096) g_rowsum[i] = 0.0f;
    if (i < NP1)          g_E[(size_t)i * SSTR + N_PTS] = eb;
    else if (i < 2 * NP1) g_E[(size_t)N_PTS * SSTR + (i - NP1)] = eb;
}

// ---------------- HMMA GEMM (single bf16 pass): E = exp(10 * h0.h1) ----------------
// 128x128 CTA tile, 256 threads (2x4 warps of 64x32), PIPE=3, K=32/stage.
// Epilogue emits per-row sums via direct global atomics (fused first u-step).
__global__ void __launch_bounds__(256, 2) gemm_kernel() {
    extern __shared__ __align__(128) unsigned char dynsm[];
    const uint32_t s0 = smem_u32(dynsm);

    int tid = threadIdx.x, lane = tid & 31, wid = tid >> 5;
    int warp_m = wid >> 2, warp_n = wid & 3;
    int row0 = blockIdx.y << 7, col0 = blockIdx.x << 7;

    float acc[4][4][4] = {};

    int lr = (wid << 3) + (tid & 7);
    int lc = (tid >> 3) & 3;
    uint32_t so_base = (uint32_t)(lr * SPB + lc * 16);
    size_t   go_base = (size_t)lr * D_DIM + lc * 8;

    int a_row = (warp_m << 6) + (lane & 15);
    int a_kc  = (lane >> 4) << 3;
    int g     = lane >> 3;
    int b_rowg = (warp_n << 5) + ((g >> 1) << 3) + (lane & 7);
    int b_kcg  = (g & 1) << 3;
    int ks_x   = wid & 1;

    const size_t rbase = (size_t)row0 * D_DIM;
    const size_t cbase = (size_t)col0 * D_DIM;

    #define LOAD_STAGE(s) do {                                                 \
        int _kb = (s) << 5;                                                    \
        const __nv_bfloat16* _A = g_h0 + rbase + _kb;                          \
        const __nv_bfloat16* _B = g_h1 + cbase + _kb;                          \
        uint32_t _sa = s0 + (uint32_t)((s) % PIPE) * SLOT;                     \
        CP_ASYNC16(_sa + so_base,            _A + go_base);                    \
        CP_ASYNC16(_sa + so_base + 64 * SPB, _A + go_base + 64 * D_DIM);       \
        CP_ASYNC16(_sa + TILB + so_base,            _B + go_base);             \
        CP_ASYNC16(_sa + TILB + so_base + 64 * SPB, _B + go_base + 64 * D_DIM);\
        CP_COMMIT();                                                           \
    } while (0)

    LOAD_STAGE(0);
    LOAD_STAGE(1);

    for (int s = 0; s < NSTG; s++) {
        if (s == NSTG - 1) CP_WAIT0(); else CP_WAIT1();
        __syncthreads();
        if (s + 2 < NSTG) LOAD_STAGE(s + 2);

        uint32_t sa = s0 + (uint32_t)(s % PIPE) * SLOT;
        #pragma unroll
        for (int kk = 0; kk < 2; kk++) {
            int ks = kk ^ ks_x;
            uint32_t af[4][4], b1[4][2];
            #pragma unroll
            for (int mt = 0; mt < 4; mt++) {
                uint32_t addr = sa + (uint32_t)((a_row + mt * 16) * SPB
                                                + (ks * 16 + a_kc) * 2);
                ldmatrix_x4(af[mt][0], af[mt][1], af[mt][2], af[mt][3], addr);
            }
            #pragma unroll
            for (int p = 0; p < 2; p++) {
                uint32_t addr = sa + TILB + (uint32_t)((b_rowg + p * 16) * SPB
                                                       + (ks * 16 + b_kcg) * 2);
                ldmatrix_x4(b1[2 * p][0], b1[2 * p][1],
                            b1[2 * p + 1][0], b1[2 * p + 1][1], addr);
            }
            #pragma unroll
            for (int mt = 0; mt < 4; mt++)
                #pragma unroll
                for (int nt = 0; nt < 4; nt++)
                    mma_16816(acc[mt][nt], af[mt], b1[nt]);
        }
    }
    #undef LOAD_STAGE

    // epilogue: E = exp(10*acc); row sums -> global atomics
    int r_lo = row0 + (warp_m << 6) + (lane >> 2);
    int c_lo = col0 + (warp_n << 5) + ((lane & 3) << 1);
    #pragma unroll
    for (int mt = 0; mt < 4; mt++) {
        float rs0 = 0.f, rs1 = 0.f;
        #pragma unroll
        for (int nt = 0; nt < 4; nt++) {
            float* p0 = g_E + (size_t)(r_lo + mt * 16) * SSTR + c_lo + nt * 8;
            float* p1 = p0 + 8 * SSTR;
            float e0 = __expf(10.f * acc[mt][nt][0]);
            float e1 = __expf(10.f * acc[mt][nt][1]);
            float e2 = __expf(10.f * acc[mt][nt][2]);
            float e3 = __expf(10.f * acc[mt][nt][3]);
            *(float2*)p0 = float2{e0, e1};
            *(float2*)p1 = float2{e2, e3};
            rs0 += e0 + e1;
            rs1 += e2 + e3;
        }
        // reduce across the lane quad (same row, 8 columns)
        rs0 += __shfl_xor_sync(0xffffffffu, rs0, 1);
        rs0 += __shfl_xor_sync(0xffffffffu, rs0, 2);
        rs1 += __shfl_xor_sync(0xffffffffu, rs1, 1);
        rs1 += __shfl_xor_sync(0xffffffffu, rs1, 2);
        if ((lane & 3) == 0) {
            atomicAdd(&g_rowsum[r_lo + mt * 16],     rs0);
            atomicAdd(&g_rowsum[r_lo + mt * 16 + 8], rs1);
        }
    }
}

// ---------------- reduce row sums -> eu1 (first u half-step) ----------------
__global__ void reduce_u1(const float* __restrict__ bin_ptr) {
    float eb = __expf(10.0f * bin_ptr[0]);
    int j = blockIdx.x * 256 + threadIdx.x;
    if (j > N_PTS) return;
    if (j < N_PTS) {
        float s = g_rowsum[j] + eb;           // + dustbin column
        g_eu[j] = __expf((LOG_MU0 - __logf(s)) * PHI);
    } else {
        float s = 4097.0f * eb;               // bin row: all entries = eb
        g_eu[j] = __expf((LOG_MU_BIN - __logf(s)) * PHI);
    }
}

// ---------------- Sinkhorn passes (MLP-batched loads) ----------------
__global__ void __launch_bounds__(256) u_pass() {
    int r = blockIdx.x;
    const float4* E4 = (const float4*)(g_E + (size_t)r * SSTR);
    const float4* V4 = (const float4*)g_ev;
    int t = threadIdx.x;
    float4 e0 = E4[t], e1 = E4[t + 256], e2 = E4[t + 512], e3 = E4[t + 768];
    float4 v0 = V4[t], v1 = V4[t + 256], v2 = V4[t + 512], v3 = V4[t + 768];
    float a0 = 0.f, a1 = 0.f, a2 = 0.f, a3 = 0.f;
    a0 = fmaf(e0.x, v0.x, a0); a1 = fmaf(e0.y, v0.y, a1);
    a2 = fmaf(e0.z, v0.z, a2); a3 = fmaf(e0.w, v0.w, a3);
    a0 = fmaf(e1.x, v1.x, a0); a1 = fmaf(e1.y, v1.y, a1);
    a2 = fmaf(e1.z, v1.z, a2); a3 = fmaf(e1.w, v1.w, a3);
    a0 = fmaf(e2.x, v2.x, a0); a1 = fmaf(e2.y, v2.y, a1);
    a2 = fmaf(e2.z, v2.z, a2); a3 = fmaf(e2.w, v2.w, a3);
    a0 = fmaf(e3.x, v3.x, a0); a1 = fmaf(e3.y, v3.y, a1);
    a2 = fmaf(e3.z, v3.z, a2); a3 = fmaf(e3.w, v3.w, a3);
    float acc = (a0 + a1) + (a2 + a3);
    if (t == 0)
        acc += g_E[(size_t)r * SSTR + N_PTS] * g_ev[N_PTS];
    __shared__ float red[8];
    #pragma unroll
    for (int o = 16; o > 0; o >>= 1) acc += __shfl_xor_sync(0xffffffffu, acc, o);
    if ((t & 31) == 0) red[t >> 5] = acc;
    __syncthreads();
    if (t == 0) {
        float tot = 0.f;
        #pragma unroll
        for (int w = 0; w < 8; w++) tot += red[w];
        float lm = (r < N_PTS) ? LOG_MU0 : LOG_MU_BIN;
        g_eu[r] = __expf((lm - __logf(tot)) * PHI);
    }
}

__global__ void __launch_bounds__(256) colsum() {
    int j  = blockIdx.x * 256 + threadIdx.x;
    int r0 = blockIdx.y * RROWS;
    int r1 = min(r0 + RROWS, NP1);
    __shared__ float ush[RROWS];
    for (int t = threadIdx.x; t < r1 - r0; t += 256) ush[t] = g_eu[r0 + t];
    __syncthreads();
    if (j >= NP1) return;
    const float* col = g_E + (size_t)r0 * SSTR + j;
    float a0 = 0.f, a1 = 0.f, a2 = 0.f, a3 = 0.f;
    float a4 = 0.f, a5 = 0.f, a6 = 0.f, a7 = 0.f;
    int n = r1 - r0, r = 0;
    for (; r + 8 <= n; r += 8) {
        float e0 = col[(size_t)(r + 0) * SSTR];
        float e1 = col[(size_t)(r + 1) * SSTR];
        float e2 = col[(size_t)(r + 2) * SSTR];
        float e3 = col[(size_t)(r + 3) * SSTR];
        float e4 = col[(size_t)(r + 4) * SSTR];
        float e5 = col[(size_t)(r + 5) * SSTR];
        float e6 = col[(size_t)(r + 6) * SSTR];
        float e7 = col[(size_t)(r + 7) * SSTR];
        a0 = fmaf(e0, ush[r + 0], a0);
        a1 = fmaf(e1, ush[r + 1], a1);
        a2 = fmaf(e2, ush[r + 2], a2);
        a3 = fmaf(e3, ush[r + 3], a3);
        a4 = fmaf(e4, ush[r + 4], a4);
        a5 = fmaf(e5, ush[r + 5], a5);
        a6 = fmaf(e6, ush[r + 6], a6);
        a7 = fmaf(e7, ush[r + 7], a7);
    }
    for (; r < n; r++) a0 = fmaf(col[(size_t)r * SSTR], ush[r], a0);
    g_part[blockIdx.y * PSTR + j] = ((a0 + a1) + (a2 + a3)) + ((a4 + a5) + (a6 + a7));
}

__global__ void v_final() {
    int j = blockIdx.x * 256 + threadIdx.x;
    if (j >= NP1) return;
    float tot = 0.f;
    #pragma unroll
    for (int c = 0; c < RCHUNKS; c++) tot += g_part[c * PSTR + j];
    float ln = (j < N_PTS) ? LOG_MU0 : LOG_MU_BIN;
    g_ev[j] = __expf((ln - __logf(tot)) * PHI);
}

// ---------------- fused last u-half-step + output ----------------
__global__ void __launch_bounds__(256) fused_final(float* __restrict__ out) {
    int r = blockIdx.x;
    const float* Er = g_E + (size_t)r * SSTR;
    const float4* E4 = (const float4*)Er;
    const float4* V4 = (const float4*)g_ev;
    int t = threadIdx.x;
    float4 e0 = E4[t], e1 = E4[t + 256], e2 = E4[t + 512], e3 = E4[t + 768];
    float4 v0 = V4[t], v1 = V4[t + 256], v2 = V4[t + 512], v3 = V4[t + 768];
    float a0 = 0.f, a1 = 0.f, a2 = 0.f, a3 = 0.f;
    a0 = fmaf(e0.x, v0.x, a0); a1 = fmaf(e0.y, v0.y, a1);
    a2 = fmaf(e0.z, v0.z, a2); a3 = fmaf(e0.w, v0.w, a3);
    a0 = fmaf(e1.x, v1.x, a0); a1 = fmaf(e1.y, v1.y, a1);
    a2 = fmaf(e1.z, v1.z, a2); a3 = fmaf(e1.w, v1.w, a3);
    a0 = fmaf(e2.x, v2.x, a0); a1 = fmaf(e2.y, v2.y, a1);
    a2 = fmaf(e2.z, v2.z, a2); a3 = fmaf(e2.w, v2.w, a3);
    a0 = fmaf(e3.x, v3.x, a0); a1 = fmaf(e3.y, v3.y, a1);
    a2 = fmaf(e3.z, v3.z, a2); a3 = fmaf(e3.w, v3.w, a3);
    float acc = (a0 + a1) + (a2 + a3);
    if (t == 0)
        acc += Er[N_PTS] * g_ev[N_PTS];
    __shared__ float red[8];
    __shared__ float s_eu;
    #pragma unroll
    for (int o = 16; o > 0; o >>= 1) acc += __shfl_xor_sync(0xffffffffu, acc, o);
    if ((t & 31) == 0) red[t >> 5] = acc;
    __syncthreads();
    if (t == 0) {
        float tot = 0.f;
        #pragma unroll
        for (int w = 0; w < 8; w++) tot += red[w];
        float lm = (r < N_PTS) ? LOG_MU0 : LOG_MU_BIN;
        s_eu = __expf((lm - __logf(tot)) * PHI);
    }
    __syncthreads();
    float eur = s_eu;
    float* orow = out + (size_t)r * NP1;
    const float* vv = g_ev;
    {
        int j0 = t * 4;
        orow[j0 + 0] = e0.x * eur * vv[j0 + 0];
        orow[j0 + 1] = e0.y * eur * vv[j0 + 1];
        orow[j0 + 2] = e0.z * eur * vv[j0 + 2];
        orow[j0 + 3] = e0.w * eur * vv[j0 + 3];
        int j1 = (t + 256) * 4;
        orow[j1 + 0] = e1.x * eur * vv[j1 + 0];
        orow[j1 + 1] = e1.y * eur * vv[j1 + 1];
        orow[j1 + 2] = e1.z * eur * vv[j1 + 2];
        orow[j1 + 3] = e1.w * eur * vv[j1 + 3];
        int j2 = (t + 512) * 4;
        orow[j2 + 0] = e2.x * eur * vv[j2 + 0];
        orow[j2 + 1] = e2.y * eur * vv[j2 + 1];
        orow[j2 + 2] = e2.z * eur * vv[j2 + 2];
        orow[j2 + 3] = e2.w * eur * vv[j2 + 3];
        int j3 = (t + 768) * 4;
        orow[j3 + 0] = e3.x * eur * vv[j3 + 0];
        orow[j3 + 1] = e3.y * eur * vv[j3 + 1];
        orow[j3 + 2] = e3.z * eur * vv[j3 + 2];
        orow[j3 + 3] = e3.w * eur * vv[j3 + 3];
    }
    if (t == 0) {
        float val = Er[N_PTS] * eur * vv[N_PTS];
        if (r == N_PTS) val = 0.0f;
        orow[N_PTS] = val;
    }
}

// ---------------- launch ----------------
extern "C" void kernel_launch(void* const* d_in, const int* in_sizes, int n_in,
                              void* d_out, int out_size) {
    const float* ft0 = (const float*)d_in[0];
    const float* ft1 = (const float*)d_in[1];
    const float* bin = (const float*)d_in[2];
    float* out = (float*)d_out;

    cudaFuncSetAttribute(gemm_kernel, cudaFuncAttributeMaxDynamicSharedMemorySize, GSMEM);

    normalize_kernel<<<2 * N_PTS, 128>>>(ft0, ft1);
    setup_kernel<<<(2 * NP1 + 255) / 256, 256>>>(bin);
    dim3 gg(32, 32);
    gemm_kernel<<<gg, 256, GSMEM>>>();

    // fused first half-step: row sums accumulated by GEMM epilogue atomics
    reduce_u1<<<17, 256>>>(bin);

    // remaining schedule: v1, u2, v2, (u3 fused with output)
    colsum<<<dim3(17, RCHUNKS), 256>>>();
    v_final<<<17, 256>>>();
    u_pass<<<NP1, 256>>>();
    colsum<<<dim3(17, RCHUNKS), 256>>>();
    v_final<<<17, 256>>>();
    fused_final<<<NP1, 256>>>(out);
}